// round 15
// baseline (speedup 1.0000x reference)
#include <cuda_runtime.h>
#include <cstdint>

// NodeDropout: out[e] = values[e] * keep[src[e]] * keep[dst[e]],  keep[i] = !nodes_flag[i]
//
// Layout (pinned by R4-R6 evidence on this bench):
//   d_in[0] : edge_index  (2, E) row-major, int32
//   d_in[1] : values      float32, E
//   d_in[2] : nodes_flag  N x 4-byte words (nonzero = dropped)
// Output: float32, E.
//
// K1: pack flag words -> full keep-bitmask in a __device__ global (~122 KB).
// K2: TWO CTAs per SM (768 threads each, 96 KB dyn smem each -> 48 warps/SM,
//     192 KB smem/SM leaves >=32 KB L1). Each CTA stages the LOW 96 KB of the
//     bitmask (nodes < 786,432) in shared memory; the ~21% of lookups at
//     nodes >= SPLIT hit the 26.7 KB bitmask tail via __ldg (L1-resident).
//     The extra 16 warps/SM buy the latency hiding the 1-CTA design lacked.

#define MAX_BIT_WORDS 32768              // up to 1,048,576 nodes
#define SPLIT_WORDS   24576              // 96 KB staged in smem
#define SPLIT_NODES   (SPLIT_WORDS * 32) // 786,432

__device__ uint32_t g_keep_bits[MAX_BIT_WORDS];

// ---------------------------------------------------------------------------
// K1: pack 4-byte flags -> keep bitmask (bit = 1 means node is KEPT)
// ---------------------------------------------------------------------------
__global__ void pack_flags_kernel(const uint32_t* __restrict__ flags,
                                  int n_nodes, int n_words) {
    int t = blockIdx.x * blockDim.x + threadIdx.x;
    if (t >= n_words) return;

    const int base = t * 32;
    uint32_t  w    = 0;

    if (base + 32 <= n_nodes) {
        const uint4* p = reinterpret_cast<const uint4*>(flags + base);  // 128 B
#pragma unroll
        for (int c = 0; c < 8; c++) {
            uint4 q = p[c];
            w |= (q.x ? 0u : 1u) << (c * 4 + 0);
            w |= (q.y ? 0u : 1u) << (c * 4 + 1);
            w |= (q.z ? 0u : 1u) << (c * 4 + 2);
            w |= (q.w ? 0u : 1u) << (c * 4 + 3);
        }
    } else {
        int lim = n_nodes - base;
        for (int j = 0; j < 32; j++) {
            uint32_t fv = (j < lim) ? flags[base + j] : 1u;  // OOB = dropped
            w |= (fv ? 0u : 1u) << j;
        }
    }
    g_keep_bits[t] = w;
}

// ---------------------------------------------------------------------------
// K2: masked edge scaling; smem-resident low bitmask + L1-resident tail
// ---------------------------------------------------------------------------
__device__ __forceinline__ uint32_t bit_of(const uint32_t* __restrict__ s_bits,
                                           uint32_t idx) {
    uint32_t word = (idx < (uint32_t)SPLIT_NODES)
                        ? s_bits[idx >> 5]
                        : __ldg(&g_keep_bits[idx >> 5]);   // 26.7 KB tail, L1-hot
    return word >> (idx & 31);
}

__device__ __forceinline__ uint32_t keep2(const uint32_t* __restrict__ s_bits,
                                          uint32_t s, uint32_t d) {
    return bit_of(s_bits, s) & bit_of(s_bits, d) & 1u;
}

__device__ __forceinline__ void do_quad(const int* __restrict__ src,
                                        const int* __restrict__ dst,
                                        const float* __restrict__ vals,
                                        float* __restrict__ out,
                                        const uint32_t* __restrict__ s_bits,
                                        int e) {
    int4   s4 = *reinterpret_cast<const int4*>(src + e);
    int4   d4 = *reinterpret_cast<const int4*>(dst + e);
    float4 v  = *reinterpret_cast<const float4*>(vals + e);

    uint32_t ka = keep2(s_bits, (uint32_t)s4.x, (uint32_t)d4.x);
    uint32_t kb = keep2(s_bits, (uint32_t)s4.y, (uint32_t)d4.y);
    uint32_t kc = keep2(s_bits, (uint32_t)s4.z, (uint32_t)d4.z);
    uint32_t kd = keep2(s_bits, (uint32_t)s4.w, (uint32_t)d4.w);

    float4 o;
    o.x = ka ? v.x : 0.0f;
    o.y = kb ? v.y : 0.0f;
    o.z = kc ? v.z : 0.0f;
    o.w = kd ? v.w : 0.0f;
    *reinterpret_cast<float4*>(out + e) = o;
}

#define CTA_THREADS 768

__global__ __launch_bounds__(CTA_THREADS, 2)
void node_dropout_kernel(const int* __restrict__ ei,
                         const float* __restrict__ vals,
                         float* __restrict__ out,
                         int E) {
    extern __shared__ uint32_t s_bits[];

    // Stage the low 96 KB of the bitmask (coalesced; L2-hot after pack).
    for (int i = threadIdx.x; i < SPLIT_WORDS; i += blockDim.x)
        s_bits[i] = g_keep_bits[i];
    __syncthreads();

    const int* __restrict__ src = ei;
    const int* __restrict__ dst = ei + E;

    const int quads  = E >> 2;
    const int stride = gridDim.x * blockDim.x;
    int       q      = blockIdx.x * blockDim.x + threadIdx.x;

    // Dual-quad grid-stride: 6 independent 128-bit loads in flight per thread.
    for (; q + stride < quads; q += 2 * stride) {
        do_quad(src, dst, vals, out, s_bits, q << 2);
        do_quad(src, dst, vals, out, s_bits, (q + stride) << 2);
    }
    if (q < quads)
        do_quad(src, dst, vals, out, s_bits, q << 2);

    // Tail edges (E % 4).
    int gtid = blockIdx.x * blockDim.x + threadIdx.x;
    int e = (quads << 2) + gtid;
    if (e < E) {
        uint32_t k = keep2(s_bits, (uint32_t)src[e], (uint32_t)dst[e]);
        out[e] = k ? vals[e] : 0.0f;
    }
}

// ---------------------------------------------------------------------------
// Launch
// ---------------------------------------------------------------------------
extern "C" void kernel_launch(void* const* d_in, const int* in_sizes, int n_in,
                              void* d_out, int out_size) {
    const int*      ei    = (const int*)d_in[0];
    const float*    vals  = (const float*)d_in[1];
    const uint32_t* flags = (const uint32_t*)d_in[2];
    float*          out   = (float*)d_out;

    const int E       = in_sizes[0] / 2;
    const int n_nodes = in_sizes[2];
    const int n_words = (n_nodes + 31) / 32;

    // K1: pack flags into keep-bitmask
    {
        int threads = 256;
        int blocks  = (n_words + threads - 1) / threads;
        pack_flags_kernel<<<blocks, threads>>>(flags, n_nodes, n_words);
    }

    // K2: masked scaling, 2 CTAs/SM (96 KB dyn smem each)
    {
        int sm_count = 148;
        cudaDeviceGetAttribute(&sm_count, cudaDevAttrMultiProcessorCount, 0);

        size_t smem_bytes = (size_t)SPLIT_WORDS * sizeof(uint32_t);   // 96 KB
        cudaFuncSetAttribute(node_dropout_kernel,
                             cudaFuncAttributeMaxDynamicSharedMemorySize,
                             (int)smem_bytes);

        node_dropout_kernel<<<2 * sm_count, CTA_THREADS, smem_bytes>>>(ei, vals, out, E);
    }
}

// round 16
// speedup vs baseline: 1.0331x; 1.0331x over previous
#include <cuda_runtime.h>
#include <cstdint>

// NodeDropout: out[e] = values[e] * keep[src[e]] * keep[dst[e]],  keep[i] = !nodes_flag[i]
//
// Layout (pinned by R4-R6 evidence on this bench):
//   d_in[0] : edge_index  (2, E) row-major, int32
//   d_in[1] : values      float32, E
//   d_in[2] : nodes_flag  N x 4-byte words (nonzero = dropped)
// Output: float32, E.
//
// K1: pack flag words -> full keep-bitmask in a __device__ global (~122 KB).
// K2: MAX OCCUPANCY config: 2 CTAs/SM x 1024 threads = 64 warps/SM (HW max),
//     32 regs/thread (RF = 65,536 exactly). Each CTA stages the low 96 KB of
//     the bitmask in smem (192 KB/SM, >=32 KB L1 left); lookups for nodes >=
//     786,432 (~21%) read the 26.7 KB bitmask tail via __ldg (L1-resident —
//     streaming traffic uses .cs evict-first to keep it hot). Single-quad
//     body: warp-level parallelism supplies the MLP the dual-quad ILP did.

#define MAX_BIT_WORDS 32768              // up to 1,048,576 nodes
#define SPLIT_WORDS   24576              // 96 KB staged in smem
#define SPLIT_NODES   (SPLIT_WORDS * 32) // 786,432

__device__ uint32_t g_keep_bits[MAX_BIT_WORDS];

// ---------------------------------------------------------------------------
// K1: pack 4-byte flags -> keep bitmask (bit = 1 means node is KEPT)
// ---------------------------------------------------------------------------
__global__ void pack_flags_kernel(const uint32_t* __restrict__ flags,
                                  int n_nodes, int n_words) {
    int t = blockIdx.x * blockDim.x + threadIdx.x;
    if (t >= n_words) return;

    const int base = t * 32;
    uint32_t  w    = 0;

    if (base + 32 <= n_nodes) {
        const uint4* p = reinterpret_cast<const uint4*>(flags + base);  // 128 B
#pragma unroll
        for (int c = 0; c < 8; c++) {
            uint4 q = p[c];
            w |= (q.x ? 0u : 1u) << (c * 4 + 0);
            w |= (q.y ? 0u : 1u) << (c * 4 + 1);
            w |= (q.z ? 0u : 1u) << (c * 4 + 2);
            w |= (q.w ? 0u : 1u) << (c * 4 + 3);
        }
    } else {
        int lim = n_nodes - base;
        for (int j = 0; j < 32; j++) {
            uint32_t fv = (j < lim) ? flags[base + j] : 1u;  // OOB = dropped
            w |= (fv ? 0u : 1u) << j;
        }
    }
    g_keep_bits[t] = w;
}

// ---------------------------------------------------------------------------
// K2: masked edge scaling; smem-resident low bitmask + L1-resident tail
// ---------------------------------------------------------------------------
__device__ __forceinline__ uint32_t bit_of(const uint32_t* __restrict__ s_bits,
                                           uint32_t idx) {
    uint32_t word = (idx < (uint32_t)SPLIT_NODES)
                        ? s_bits[idx >> 5]
                        : __ldg(&g_keep_bits[idx >> 5]);   // 26.7 KB tail, L1-hot
    return word >> (idx & 31);
}

__device__ __forceinline__ uint32_t keep2(const uint32_t* __restrict__ s_bits,
                                          uint32_t s, uint32_t d) {
    return bit_of(s_bits, s) & bit_of(s_bits, d) & 1u;
}

#define CTA_THREADS 1024

__global__ __launch_bounds__(CTA_THREADS, 2)   // 32-reg cap -> 64 warps/SM
void node_dropout_kernel(const int* __restrict__ ei,
                         const float* __restrict__ vals,
                         float* __restrict__ out,
                         int E) {
    extern __shared__ uint32_t s_bits[];

    // Stage the low 96 KB of the bitmask (coalesced; L2-hot after pack).
    for (int i = threadIdx.x; i < SPLIT_WORDS; i += blockDim.x)
        s_bits[i] = g_keep_bits[i];
    __syncthreads();

    const int* __restrict__ src = ei;
    const int* __restrict__ dst = ei + E;

    const int quads  = E >> 2;
    const int stride = gridDim.x * blockDim.x;
    int       q      = blockIdx.x * blockDim.x + threadIdx.x;

    // Single-quad grid-stride: minimal live registers; 64 warps/SM supply MLP.
    for (; q < quads; q += stride) {
        const int e = q << 2;

        int4   s4 = __ldcs(reinterpret_cast<const int4*>(src + e));
        int4   d4 = __ldcs(reinterpret_cast<const int4*>(dst + e));
        float4 v  = __ldcs(reinterpret_cast<const float4*>(vals + e));

        uint32_t ka = keep2(s_bits, (uint32_t)s4.x, (uint32_t)d4.x);
        uint32_t kb = keep2(s_bits, (uint32_t)s4.y, (uint32_t)d4.y);
        uint32_t kc = keep2(s_bits, (uint32_t)s4.z, (uint32_t)d4.z);
        uint32_t kd = keep2(s_bits, (uint32_t)s4.w, (uint32_t)d4.w);

        float4 o;
        o.x = ka ? v.x : 0.0f;
        o.y = kb ? v.y : 0.0f;
        o.z = kc ? v.z : 0.0f;
        o.w = kd ? v.w : 0.0f;
        __stcs(reinterpret_cast<float4*>(out + e), o);
    }

    // Tail edges (E % 4).
    int gtid = blockIdx.x * blockDim.x + threadIdx.x;
    int e = (quads << 2) + gtid;
    if (e < E) {
        uint32_t k = keep2(s_bits, (uint32_t)src[e], (uint32_t)dst[e]);
        out[e] = k ? vals[e] : 0.0f;
    }
}

// ---------------------------------------------------------------------------
// Launch
// ---------------------------------------------------------------------------
extern "C" void kernel_launch(void* const* d_in, const int* in_sizes, int n_in,
                              void* d_out, int out_size) {
    const int*      ei    = (const int*)d_in[0];
    const float*    vals  = (const float*)d_in[1];
    const uint32_t* flags = (const uint32_t*)d_in[2];
    float*          out   = (float*)d_out;

    const int E       = in_sizes[0] / 2;
    const int n_nodes = in_sizes[2];
    const int n_words = (n_nodes + 31) / 32;

    // K1: pack flags into keep-bitmask
    {
        int threads = 256;
        int blocks  = (n_words + threads - 1) / threads;
        pack_flags_kernel<<<blocks, threads>>>(flags, n_nodes, n_words);
    }

    // K2: masked scaling, 2 CTAs/SM x 1024 threads (64 warps/SM)
    {
        int sm_count = 148;
        cudaDeviceGetAttribute(&sm_count, cudaDevAttrMultiProcessorCount, 0);

        size_t smem_bytes = (size_t)SPLIT_WORDS * sizeof(uint32_t);   // 96 KB
        cudaFuncSetAttribute(node_dropout_kernel,
                             cudaFuncAttributeMaxDynamicSharedMemorySize,
                             (int)smem_bytes);

        node_dropout_kernel<<<2 * sm_count, CTA_THREADS, smem_bytes>>>(ei, vals, out, E);
    }
}